// round 1
// baseline (speedup 1.0000x reference)
#include <cuda_runtime.h>
#include <math.h>

#define NHEADS 16
#define BSZ    2
#define SEQ    2048
#define CDIM   256
#define HID    1024
#define HD     64
#define ROWS   (BSZ * SEQ)   // 4096
#define QKVW   (3 * HID)     // 3072

// Scratch (allocation-free rule: __device__ globals)
__device__ float g_qkv[(size_t)ROWS * QKVW];   // 48 MB: [row][3*1024]
__device__ float g_attn[(size_t)ROWS * HID];   // 16 MB: [row][1024]

// ---------------------------------------------------------------------------
// Generic tiled GEMM: C[M,N] = A[M,K] @ B[K,N], all row-major fp32.
// BM=BN=64, BK=16, 256 threads, 4x4 micro-tile per thread.
// ---------------------------------------------------------------------------
__global__ __launch_bounds__(256) void gemm64_kernel(
    const float* __restrict__ A, const float* __restrict__ B,
    float* __restrict__ C, int M, int N, int K)
{
    __shared__ float As[16][64];   // transposed: [k][m]
    __shared__ float Bs[16][64];   // [k][n]

    const int tid  = threadIdx.x;
    const int tx   = tid & 15;     // col group
    const int ty   = tid >> 4;     // row group
    const int row0 = blockIdx.y * 64;
    const int col0 = blockIdx.x * 64;

    float acc[4][4] = {};

    for (int k0 = 0; k0 < K; k0 += 16) {
        // A tile: 64 rows x 16 k. one float4 per thread, store transposed.
        {
            int r  = tid >> 2;           // 0..63
            int kk = (tid & 3) << 2;     // 0,4,8,12
            float4 a = *(const float4*)&A[(size_t)(row0 + r) * K + k0 + kk];
            As[kk + 0][r] = a.x; As[kk + 1][r] = a.y;
            As[kk + 2][r] = a.z; As[kk + 3][r] = a.w;
        }
        // B tile: 16 k x 64 cols. one float4 per thread.
        {
            int kk = tid >> 4;           // 0..15
            int c  = (tid & 15) << 2;    // 0..60
            *(float4*)&Bs[kk][c] = *(const float4*)&B[(size_t)(k0 + kk) * N + col0 + c];
        }
        __syncthreads();

        #pragma unroll
        for (int kk = 0; kk < 16; ++kk) {
            float4 a = *(const float4*)&As[kk][ty << 2];
            float4 b = *(const float4*)&Bs[kk][tx << 2];
            acc[0][0] += a.x * b.x; acc[0][1] += a.x * b.y; acc[0][2] += a.x * b.z; acc[0][3] += a.x * b.w;
            acc[1][0] += a.y * b.x; acc[1][1] += a.y * b.y; acc[1][2] += a.y * b.z; acc[1][3] += a.y * b.w;
            acc[2][0] += a.z * b.x; acc[2][1] += a.z * b.y; acc[2][2] += a.z * b.z; acc[2][3] += a.z * b.w;
            acc[3][0] += a.w * b.x; acc[3][1] += a.w * b.y; acc[3][2] += a.w * b.z; acc[3][3] += a.w * b.w;
        }
        __syncthreads();
    }

    #pragma unroll
    for (int i = 0; i < 4; ++i) {
        float4 o = make_float4(acc[i][0], acc[i][1], acc[i][2], acc[i][3]);
        *(float4*)&C[(size_t)(row0 + (ty << 2) + i) * N + col0 + (tx << 2)] = o;
    }
}

// ---------------------------------------------------------------------------
// Flash attention, fp32. Grid: (SEQ/64, BSZ*NHEADS). 256 threads = 8 warps.
// Warp w owns 8 query rows (w*8..w*8+7); lane l owns kv/out cols {l, l+32}.
// Smem: Qs (plain, broadcast reads), Ks (XOR-swizzled by 16B chunks for
// conflict-free LDS.128 across rows; reused for P in plain layout), Vs (plain,
// row-contiguous reads are conflict-free). Exactly 48 KB static.
// ---------------------------------------------------------------------------
__global__ __launch_bounds__(256) void flash_kernel(float* __restrict__ attn_out)
{
    __shared__ float Qs[64][64];
    __shared__ float Ks[64][64];   // K (swizzled) then P (plain)
    __shared__ float Vs[64][64];

    const int tid = threadIdx.x;
    const int w   = tid >> 5;      // warp 0..7
    const int l   = tid & 31;      // lane
    const int bh  = blockIdx.y;
    const int b   = bh >> 4;
    const int h   = bh & 15;
    const int q0  = blockIdx.x * 64;
    const int rowbase = b * SEQ;

    const float* qb = g_qkv + (size_t)rowbase * QKVW + h * HD;           // q slice
    const float* kb = g_qkv + (size_t)rowbase * QKVW + HID + h * HD;     // k slice
    const float* vb = g_qkv + (size_t)rowbase * QKVW + 2 * HID + h * HD; // v slice

    // Load Q tile, fold in 1/sqrt(64)
    for (int i = tid; i < 64 * 16; i += 256) {
        int r  = i >> 4;
        int k4 = (i & 15) << 2;
        float4 v = *(const float4*)&qb[(size_t)(q0 + r) * QKVW + k4];
        v.x *= 0.125f; v.y *= 0.125f; v.z *= 0.125f; v.w *= 0.125f;
        *(float4*)&Qs[r][k4] = v;
    }

    float m_i[8], l_i[8], acc[8][2];
    #pragma unroll
    for (int i = 0; i < 8; ++i) {
        m_i[i] = -INFINITY; l_i[i] = 0.0f; acc[i][0] = 0.0f; acc[i][1] = 0.0f;
    }

    const int swz = (l & 7) << 2;

    for (int t = 0; t < SEQ / 64; ++t) {
        const int j0 = t * 64;
        __syncthreads();   // previous iteration done with Ks(P)/Vs
        // Load K (swizzled) and V (plain)
        for (int i = tid; i < 64 * 16; i += 256) {
            int r  = i >> 4;
            int k4 = (i & 15) << 2;
            float4 kv = *(const float4*)&kb[(size_t)(j0 + r) * QKVW + k4];
            *(float4*)&Ks[r][k4 ^ ((r & 7) << 2)] = kv;
            float4 vv = *(const float4*)&vb[(size_t)(j0 + r) * QKVW + k4];
            *(float4*)&Vs[r][k4] = vv;
        }
        __syncthreads();

        // S = Q @ K^T (scaled). s[i][0]: col l, s[i][1]: col l+32.
        float s[8][2] = {};
        #pragma unroll
        for (int k4 = 0; k4 < 64; k4 += 4) {
            float4 kv0 = *(const float4*)&Ks[l]     [k4 ^ swz];
            float4 kv1 = *(const float4*)&Ks[l + 32][k4 ^ swz]; // (l+32)&7 == l&7
            #pragma unroll
            for (int i = 0; i < 8; ++i) {
                float4 q = *(const float4*)&Qs[w * 8 + i][k4];
                s[i][0] += q.x * kv0.x + q.y * kv0.y + q.z * kv0.z + q.w * kv0.w;
                s[i][1] += q.x * kv1.x + q.y * kv1.y + q.z * kv1.z + q.w * kv1.w;
            }
        }

        // Online softmax (rows are warp-local: full-warp shfl reductions)
        #pragma unroll
        for (int i = 0; i < 8; ++i) {
            float mx = fmaxf(s[i][0], s[i][1]);
            #pragma unroll
            for (int off = 16; off >= 1; off >>= 1)
                mx = fmaxf(mx, __shfl_xor_sync(0xffffffffu, mx, off));
            float mnew  = fmaxf(m_i[i], mx);
            float p0    = __expf(s[i][0] - mnew);
            float p1    = __expf(s[i][1] - mnew);
            float alpha = __expf(m_i[i] - mnew);
            m_i[i] = mnew;
            float ps = p0 + p1;
            #pragma unroll
            for (int off = 16; off >= 1; off >>= 1)
                ps += __shfl_xor_sync(0xffffffffu, ps, off);
            l_i[i] = l_i[i] * alpha + ps;
            acc[i][0] *= alpha; acc[i][1] *= alpha;
            s[i][0] = p0; s[i][1] = p1;   // s now holds P
        }

        __syncthreads();   // all warps finished reading Ks before P overwrite
        #pragma unroll
        for (int i = 0; i < 8; ++i) {     // P rows are warp-private
            Ks[w * 8 + i][l]      = s[i][0];
            Ks[w * 8 + i][l + 32] = s[i][1];
        }
        __syncwarp();

        // O += P @ V
        #pragma unroll
        for (int jj = 0; jj < 64; jj += 4) {
            float4 pv[8];
            #pragma unroll
            for (int i = 0; i < 8; ++i)
                pv[i] = *(const float4*)&Ks[w * 8 + i][jj];
            #pragma unroll
            for (int u = 0; u < 4; ++u) {
                float v0 = Vs[jj + u][l];
                float v1 = Vs[jj + u][l + 32];
                #pragma unroll
                for (int i = 0; i < 8; ++i) {
                    float p = (u == 0) ? pv[i].x : (u == 1) ? pv[i].y
                            : (u == 2) ? pv[i].z : pv[i].w;
                    acc[i][0] += p * v0;
                    acc[i][1] += p * v1;
                }
            }
        }
    }

    // Epilogue: normalize, write (B,N,H,d) laid out as [row][h*64+c]
    #pragma unroll
    for (int i = 0; i < 8; ++i) {
        float inv = 1.0f / l_i[i];
        size_t gr = (size_t)(rowbase + q0 + w * 8 + i) * HID + h * HD;
        attn_out[gr + l]      = acc[i][0] * inv;
        attn_out[gr + l + 32] = acc[i][1] * inv;
    }
}

// ---------------------------------------------------------------------------
extern "C" void kernel_launch(void* const* d_in, const int* in_sizes, int n_in,
                              void* d_out, int out_size)
{
    const float* array = (const float*)d_in[0];   // (2,2048,256)
    const float* Wqkv  = (const float*)d_in[1];   // (256,3072)
    const float* Wout  = (const float*)d_in[2];   // (1024,64)
    float* out = (float*)d_out;                   // (2,2048,64)

    float *qkv, *attn;
    cudaGetSymbolAddress((void**)&qkv,  g_qkv);
    cudaGetSymbolAddress((void**)&attn, g_attn);

    // 1) qkv = array @ Wqkv   (4096x3072x256)
    gemm64_kernel<<<dim3(QKVW / 64, ROWS / 64), 256>>>(array, Wqkv, qkv,
                                                       ROWS, QKVW, CDIM);
    // 2) flash attention -> attn (4096x1024)
    flash_kernel<<<dim3(SEQ / 64, BSZ * NHEADS), 256>>>(attn);

    // 3) out = attn @ Wout    (4096x64x1024)
    gemm64_kernel<<<dim3(HD / 64, ROWS / 64), 256>>>(attn, Wout, out,
                                                     ROWS, HD, HID);
}

// round 2
// speedup vs baseline: 2.1993x; 2.1993x over previous
#include <cuda_runtime.h>
#include <math.h>
#include <stdint.h>

#define NHEADS 16
#define BSZ    2
#define SEQ    2048
#define CDIM   256
#define HID    1024
#define HD     64
#define ROWS   (BSZ * SEQ)   // 4096
#define QKVW   (3 * HID)     // 3072

// Scratch (allocation-free rule: __device__ globals)
__device__ float g_qkv[(size_t)ROWS * QKVW];   // 48 MB: [row][3*1024]
__device__ float g_attn[(size_t)ROWS * HID];   // 16 MB: [row][1024]

// ---------------------------------------------------------------------------
// Generic tiled GEMM: C[M,N] = A[M,K] @ B[K,N], fp32 (projections stay exact).
// ---------------------------------------------------------------------------
__global__ __launch_bounds__(256) void gemm64_kernel(
    const float* __restrict__ A, const float* __restrict__ B,
    float* __restrict__ C, int M, int N, int K)
{
    __shared__ float As[16][64];   // transposed: [k][m]
    __shared__ float Bs[16][64];   // [k][n]

    const int tid  = threadIdx.x;
    const int tx   = tid & 15;
    const int ty   = tid >> 4;
    const int row0 = blockIdx.y * 64;
    const int col0 = blockIdx.x * 64;

    float acc[4][4] = {};

    for (int k0 = 0; k0 < K; k0 += 16) {
        {
            int r  = tid >> 2;
            int kk = (tid & 3) << 2;
            float4 a = *(const float4*)&A[(size_t)(row0 + r) * K + k0 + kk];
            As[kk + 0][r] = a.x; As[kk + 1][r] = a.y;
            As[kk + 2][r] = a.z; As[kk + 3][r] = a.w;
        }
        {
            int kk = tid >> 4;
            int c  = (tid & 15) << 2;
            *(float4*)&Bs[kk][c] = *(const float4*)&B[(size_t)(k0 + kk) * N + col0 + c];
        }
        __syncthreads();

        #pragma unroll
        for (int kk = 0; kk < 16; ++kk) {
            float4 a = *(const float4*)&As[kk][ty << 2];
            float4 b = *(const float4*)&Bs[kk][tx << 2];
            acc[0][0] += a.x * b.x; acc[0][1] += a.x * b.y; acc[0][2] += a.x * b.z; acc[0][3] += a.x * b.w;
            acc[1][0] += a.y * b.x; acc[1][1] += a.y * b.y; acc[1][2] += a.y * b.z; acc[1][3] += a.y * b.w;
            acc[2][0] += a.z * b.x; acc[2][1] += a.z * b.y; acc[2][2] += a.z * b.z; acc[2][3] += a.z * b.w;
            acc[3][0] += a.w * b.x; acc[3][1] += a.w * b.y; acc[3][2] += a.w * b.z; acc[3][3] += a.w * b.w;
        }
        __syncthreads();
    }

    #pragma unroll
    for (int i = 0; i < 4; ++i) {
        float4 o = make_float4(acc[i][0], acc[i][1], acc[i][2], acc[i][3]);
        *(float4*)&C[(size_t)(row0 + (ty << 2) + i) * N + col0 + (tx << 2)] = o;
    }
}

// ---------------------------------------------------------------------------
// TF32 tensor-core helpers
// ---------------------------------------------------------------------------
__device__ __forceinline__ uint32_t f2tf32(float x) {
    uint32_t r;
    asm("cvt.rna.tf32.f32 %0, %1;" : "=r"(r) : "f"(x));
    return r;
}

__device__ __forceinline__ void mma_tf32(
    float* d, uint32_t a0, uint32_t a1, uint32_t a2, uint32_t a3,
    uint32_t b0, uint32_t b1)
{
    asm volatile(
        "mma.sync.aligned.m16n8k8.row.col.f32.tf32.tf32.f32 "
        "{%0,%1,%2,%3}, {%4,%5,%6,%7}, {%8,%9}, {%0,%1,%2,%3};\n"
        : "+f"(d[0]), "+f"(d[1]), "+f"(d[2]), "+f"(d[3])
        : "r"(a0), "r"(a1), "r"(a2), "r"(a3), "r"(b0), "r"(b1));
}

// ---------------------------------------------------------------------------
// Flash attention, tf32 mma. Grid: (SEQ/128, BSZ*NHEADS), 256 threads.
// Warp w owns m-tile rows [w*16, w*16+16) of the 128-row Q block and FULL
// 64-wide S rows -> warp-local online softmax.
// Smem (dynamic, tf32 bits pre-converted):
//   Ks[64][68]  B-frag reads bank = 4*(l/4)+(l%4)   -> conflict-free
//   Vs[64][72]  B-frag reads bank = 8*(l%4)+(l/4)   -> conflict-free
//   Pb[128][68] A-frag reads bank = 4*(l/4)+(l%4)   -> conflict-free
// ---------------------------------------------------------------------------
#define KS_STR 68
#define VS_STR 72
#define PB_STR 68
#define SMEM_FLOATS (64 * KS_STR + 64 * VS_STR + 128 * PB_STR)

__global__ __launch_bounds__(256, 2) void flash_tc_kernel(float* __restrict__ attn_out)
{
    extern __shared__ uint32_t sm[];
    uint32_t* KsU = sm;
    uint32_t* VsU = sm + 64 * KS_STR;
    uint32_t* PbU = sm + 64 * KS_STR + 64 * VS_STR;
    float*    Pbf = (float*)PbU;

    const int tid = threadIdx.x;
    const int w   = tid >> 5;
    const int l   = tid & 31;
    const int lr  = l >> 2;     // 0..7 (groupID)
    const int lc  = l & 3;      // 0..3
    const int bh  = blockIdx.y;
    const int b   = bh >> 4;
    const int h   = bh & 15;
    const int q0  = blockIdx.x * 128;
    const int rowbase = b * SEQ;
    const int m0  = w * 16;

    const float* qb = g_qkv + (size_t)rowbase * QKVW + h * HD;
    const float* kb = g_qkv + (size_t)rowbase * QKVW + HID + h * HD;
    const float* vb = g_qkv + (size_t)rowbase * QKVW + 2 * HID + h * HD;

    // ---- Stage Q (scaled by 1/sqrt(64)) into Pb, then lift to register frags
    for (int i = tid; i < 128 * 16; i += 256) {
        int r  = i >> 4;
        int c4 = (i & 15) << 2;
        float4 v = *(const float4*)&qb[(size_t)(q0 + r) * QKVW + c4];
        v.x *= 0.125f; v.y *= 0.125f; v.z *= 0.125f; v.w *= 0.125f;
        *(float4*)&Pbf[r * PB_STR + c4] = v;
    }
    __syncthreads();

    uint32_t qa[8][4];
    #pragma unroll
    for (int k = 0; k < 8; ++k) {
        int col = k * 8 + lc;
        qa[k][0] = f2tf32(Pbf[(m0 + lr)     * PB_STR + col]);
        qa[k][1] = f2tf32(Pbf[(m0 + lr + 8) * PB_STR + col]);
        qa[k][2] = f2tf32(Pbf[(m0 + lr)     * PB_STR + col + 4]);
        qa[k][3] = f2tf32(Pbf[(m0 + lr + 8) * PB_STR + col + 4]);
    }

    float oacc[8][4];
    #pragma unroll
    for (int nt = 0; nt < 8; ++nt)
        oacc[nt][0] = oacc[nt][1] = oacc[nt][2] = oacc[nt][3] = 0.0f;
    float m0r = -INFINITY, m1r = -INFINITY, l0r = 0.0f, l1r = 0.0f;

    for (int t = 0; t < SEQ / 64; ++t) {
        const int j0 = t * 64;
        __syncthreads();   // prev iter done reading Vs / Pb; done reading Ks

        // ---- Load K and V tiles, convert to tf32 bits
        for (int i = tid; i < 64 * 16; i += 256) {
            int r  = i >> 4;
            int c4 = (i & 15) << 2;
            float4 kv = *(const float4*)&kb[(size_t)(j0 + r) * QKVW + c4];
            uint4 ku = make_uint4(f2tf32(kv.x), f2tf32(kv.y), f2tf32(kv.z), f2tf32(kv.w));
            *(uint4*)&KsU[r * KS_STR + c4] = ku;
            float4 vv = *(const float4*)&vb[(size_t)(j0 + r) * QKVW + c4];
            uint4 vu = make_uint4(f2tf32(vv.x), f2tf32(vv.y), f2tf32(vv.z), f2tf32(vv.w));
            *(uint4*)&VsU[r * VS_STR + c4] = vu;
        }
        __syncthreads();

        // ---- S = Q @ K^T : warp computes 16x64
        float sa[8][4];
        #pragma unroll
        for (int nt = 0; nt < 8; ++nt) {
            sa[nt][0] = sa[nt][1] = sa[nt][2] = sa[nt][3] = 0.0f;
            const uint32_t* krow = &KsU[(nt * 8 + lr) * KS_STR + lc];
            #pragma unroll
            for (int k = 0; k < 8; ++k) {
                uint32_t b0 = krow[k * 8];
                uint32_t b1 = krow[k * 8 + 4];
                mma_tf32(sa[nt], qa[k][0], qa[k][1], qa[k][2], qa[k][3], b0, b1);
            }
        }

        // ---- Online softmax (rows r0=m0+lr, r1=m0+lr+8; quad owns full row)
        float mx0 = -INFINITY, mx1 = -INFINITY;
        #pragma unroll
        for (int nt = 0; nt < 8; ++nt) {
            mx0 = fmaxf(mx0, fmaxf(sa[nt][0], sa[nt][1]));
            mx1 = fmaxf(mx1, fmaxf(sa[nt][2], sa[nt][3]));
        }
        mx0 = fmaxf(mx0, __shfl_xor_sync(0xffffffffu, mx0, 1));
        mx0 = fmaxf(mx0, __shfl_xor_sync(0xffffffffu, mx0, 2));
        mx1 = fmaxf(mx1, __shfl_xor_sync(0xffffffffu, mx1, 1));
        mx1 = fmaxf(mx1, __shfl_xor_sync(0xffffffffu, mx1, 2));

        float mn0 = fmaxf(m0r, mx0);
        float mn1 = fmaxf(m1r, mx1);
        float a0  = __expf(m0r - mn0);
        float a1  = __expf(m1r - mn1);
        m0r = mn0; m1r = mn1;

        float ps0 = 0.0f, ps1 = 0.0f;
        #pragma unroll
        for (int nt = 0; nt < 8; ++nt) {
            sa[nt][0] = __expf(sa[nt][0] - mn0);
            sa[nt][1] = __expf(sa[nt][1] - mn0);
            sa[nt][2] = __expf(sa[nt][2] - mn1);
            sa[nt][3] = __expf(sa[nt][3] - mn1);
            ps0 += sa[nt][0] + sa[nt][1];
            ps1 += sa[nt][2] + sa[nt][3];
        }
        ps0 += __shfl_xor_sync(0xffffffffu, ps0, 1);
        ps0 += __shfl_xor_sync(0xffffffffu, ps0, 2);
        ps1 += __shfl_xor_sync(0xffffffffu, ps1, 1);
        ps1 += __shfl_xor_sync(0xffffffffu, ps1, 2);
        l0r = l0r * a0 + ps0;
        l1r = l1r * a1 + ps1;

        #pragma unroll
        for (int nt = 0; nt < 8; ++nt) {
            oacc[nt][0] *= a0; oacc[nt][1] *= a0;
            oacc[nt][2] *= a1; oacc[nt][3] *= a1;
        }

        // ---- Write P (tf32 bits) into warp-private rows of Pb
        #pragma unroll
        for (int nt = 0; nt < 8; ++nt) {
            uint2 p0 = make_uint2(f2tf32(sa[nt][0]), f2tf32(sa[nt][1]));
            uint2 p1 = make_uint2(f2tf32(sa[nt][2]), f2tf32(sa[nt][3]));
            *(uint2*)&PbU[(m0 + lr)     * PB_STR + nt * 8 + 2 * lc] = p0;
            *(uint2*)&PbU[(m0 + lr + 8) * PB_STR + nt * 8 + 2 * lc] = p1;
        }
        __syncwarp();

        // ---- O += P @ V
        #pragma unroll
        for (int k = 0; k < 8; ++k) {
            int col = k * 8 + lc;
            uint32_t pa0 = PbU[(m0 + lr)     * PB_STR + col];
            uint32_t pa1 = PbU[(m0 + lr + 8) * PB_STR + col];
            uint32_t pa2 = PbU[(m0 + lr)     * PB_STR + col + 4];
            uint32_t pa3 = PbU[(m0 + lr + 8) * PB_STR + col + 4];
            const uint32_t* v0 = &VsU[(k * 8 + lc)     * VS_STR + lr];
            const uint32_t* v1 = &VsU[(k * 8 + lc + 4) * VS_STR + lr];
            #pragma unroll
            for (int nt = 0; nt < 8; ++nt) {
                mma_tf32(oacc[nt], pa0, pa1, pa2, pa3, v0[nt * 8], v1[nt * 8]);
            }
        }
    }

    // ---- Epilogue: normalize, write [row][h*64 + col]
    float inv0 = 1.0f / l0r;
    float inv1 = 1.0f / l1r;
    size_t gr0 = (size_t)(rowbase + q0 + m0 + lr)     * HID + h * HD;
    size_t gr1 = (size_t)(rowbase + q0 + m0 + lr + 8) * HID + h * HD;
    #pragma unroll
    for (int nt = 0; nt < 8; ++nt) {
        int c = nt * 8 + 2 * lc;
        *(float2*)&attn_out[gr0 + c] = make_float2(oacc[nt][0] * inv0, oacc[nt][1] * inv0);
        *(float2*)&attn_out[gr1 + c] = make_float2(oacc[nt][2] * inv1, oacc[nt][3] * inv1);
    }
}

// ---------------------------------------------------------------------------
extern "C" void kernel_launch(void* const* d_in, const int* in_sizes, int n_in,
                              void* d_out, int out_size)
{
    const float* array = (const float*)d_in[0];   // (2,2048,256)
    const float* Wqkv  = (const float*)d_in[1];   // (256,3072)
    const float* Wout  = (const float*)d_in[2];   // (1024,64)
    float* out = (float*)d_out;                   // (2,2048,64)

    float *qkv, *attn;
    cudaGetSymbolAddress((void**)&qkv,  g_qkv);
    cudaGetSymbolAddress((void**)&attn, g_attn);

    cudaFuncSetAttribute(flash_tc_kernel,
                         cudaFuncAttributeMaxDynamicSharedMemorySize,
                         SMEM_FLOATS * 4);

    // 1) qkv = array @ Wqkv   (4096x3072x256)
    gemm64_kernel<<<dim3(QKVW / 64, ROWS / 64), 256>>>(array, Wqkv, qkv,
                                                       ROWS, QKVW, CDIM);
    // 2) flash attention (tf32 tensor cores) -> attn (4096x1024)
    flash_tc_kernel<<<dim3(SEQ / 128, BSZ * NHEADS), 256, SMEM_FLOATS * 4>>>(attn);

    // 3) out = attn @ Wout    (4096x64x1024)
    gemm64_kernel<<<dim3(HD / 64, ROWS / 64), 256>>>(attn, Wout, out,
                                                     ROWS, HD, HID);
}